// round 12
// baseline (speedup 1.0000x reference)
#include <cuda_runtime.h>
#include <cuda_fp16.h>
#include <cstdint>

// ============================ problem constants ============================
#define TOKENS 8192
#define IN_F   4096
#define OUT_F  4096
#define RANK   16

// ============================ scratch (device globals) =====================
__device__ __align__(1024) __half g_xh[(size_t)TOKENS * IN_F];  // x in fp16
__device__ __align__(1024) __half g_wh[(size_t)OUT_F * IN_F];   // fused W in fp16

// ============================ PTX helpers ==================================
__device__ __forceinline__ uint32_t smem_u32(const void* p) {
    uint32_t a;
    asm("{ .reg .u64 t; cvta.to.shared.u64 t, %1; cvt.u32.u64 %0, t; }" : "=r"(a) : "l"(p));
    return a;
}
__device__ __forceinline__ void cp_async16(uint32_t dst, const void* src) {
    asm volatile("cp.async.cg.shared.global [%0], [%1], 16;" :: "r"(dst), "l"(src) : "memory");
}
__device__ __forceinline__ void cp_commit() {
    asm volatile("cp.async.commit_group;" ::: "memory");
}
__device__ __forceinline__ void cp_wait1() {
    asm volatile("cp.async.wait_group 1;" ::: "memory");
}
__device__ __forceinline__ void ldsm_x4(uint32_t& r0, uint32_t& r1, uint32_t& r2, uint32_t& r3,
                                        uint32_t addr) {
    asm volatile("ldmatrix.sync.aligned.m8n8.x4.shared.b16 {%0,%1,%2,%3}, [%4];"
                 : "=r"(r0), "=r"(r1), "=r"(r2), "=r"(r3) : "r"(addr));
}
__device__ __forceinline__ void mma16816(float* c, const uint32_t* a, const uint32_t* b) {
    asm volatile(
        "mma.sync.aligned.m16n8k16.row.col.f32.f16.f16.f32 "
        "{%0,%1,%2,%3}, {%4,%5,%6,%7}, {%8,%9}, {%0,%1,%2,%3};"
        : "+f"(c[0]), "+f"(c[1]), "+f"(c[2]), "+f"(c[3])
        : "r"(a[0]), "r"(a[1]), "r"(a[2]), "r"(a[3]), "r"(b[0]), "r"(b[1]));
}

// ============================ kernel 1: x -> fp16 ==========================
__global__ void __launch_bounds__(256) prep_x_kernel(const float* __restrict__ x) {
    size_t base = ((size_t)blockIdx.x * 256 + threadIdx.x) * 8;
    float4 v0 = *reinterpret_cast<const float4*>(x + base);
    float4 v1 = *reinterpret_cast<const float4*>(x + base + 4);
    __half2 h0 = __floats2half2_rn(v0.x, v0.y);
    __half2 h1 = __floats2half2_rn(v0.z, v0.w);
    __half2 h2 = __floats2half2_rn(v1.x, v1.y);
    __half2 h3 = __floats2half2_rn(v1.z, v1.w);
    uint4 o;
    o.x = reinterpret_cast<uint32_t&>(h0);
    o.y = reinterpret_cast<uint32_t&>(h1);
    o.z = reinterpret_cast<uint32_t&>(h2);
    o.w = reinterpret_cast<uint32_t&>(h3);
    *reinterpret_cast<uint4*>(&g_xh[base]) = o;
}

// ====== kernel 2: W = alpha*T + mu + lora_B @ lora_A (fp16), tiled 64x64 ===
__global__ void __launch_bounds__(256) build_w_kernel(
    const int*   __restrict__ packed,   // [OUT_F, 256]
    const float* __restrict__ alpha,    // [OUT_F]
    const float* __restrict__ mu,       // [OUT_F]
    const float* __restrict__ loraA,    // [RANK, IN_F]
    const float* __restrict__ loraB)    // [OUT_F, RANK]
{
    __shared__ float sA[RANK][64];
    __shared__ float sB[64][RANK];
    const int tid = threadIdx.x;
    const int i0 = blockIdx.x * 64;
    const int o0 = blockIdx.y * 64;

    for (int i = tid; i < RANK * 64; i += 256) {
        int r = i >> 6, j = i & 63;
        sA[r][j] = loraA[(size_t)r * IN_F + i0 + j];
    }
    for (int i = tid; i < 64 * RANK; i += 256) {
        int o = i >> 4, r = i & 15;
        sB[o][r] = loraB[(size_t)(o0 + o) * RANK + r];
    }
    __syncthreads();

    const int ol = tid >> 2;
    const int ig = tid & 3;
    const int o  = o0 + ol;
    const float a = alpha[o];
    const float m = mu[o];
    const int word = packed[(size_t)o * 256 + (i0 >> 4) + ig];

    float acc[16];
#pragma unroll
    for (int k = 0; k < 16; ++k)
        acc[k] = m + a * (float)(((word >> (2 * k)) & 3) - 1);

#pragma unroll
    for (int r = 0; r < RANK; ++r) {
        const float br = sB[ol][r];
        const float* arow = &sA[r][ig * 16];
#pragma unroll
        for (int k = 0; k < 16; ++k) acc[k] += br * arow[k];
    }

    __half2 hh[8];
#pragma unroll
    for (int k = 0; k < 8; ++k) hh[k] = __floats2half2_rn(acc[2 * k], acc[2 * k + 1]);
    uint4 u0, u1;
    u0.x = reinterpret_cast<uint32_t&>(hh[0]); u0.y = reinterpret_cast<uint32_t&>(hh[1]);
    u0.z = reinterpret_cast<uint32_t&>(hh[2]); u0.w = reinterpret_cast<uint32_t&>(hh[3]);
    u1.x = reinterpret_cast<uint32_t&>(hh[4]); u1.y = reinterpret_cast<uint32_t&>(hh[5]);
    u1.z = reinterpret_cast<uint32_t&>(hh[6]); u1.w = reinterpret_cast<uint32_t&>(hh[7]);
    __half* wrow = g_wh + (size_t)o * IN_F + i0 + ig * 16;
    *reinterpret_cast<uint4*>(wrow)     = u0;
    *reinterpret_cast<uint4*>(wrow + 8) = u1;
}

// ============================ kernel 3: GEMM (mma.sync HMMA) ===============
// CTA tile 128(M) x 256(N), BK=64, 3-stage cp.async pipeline, 16 warps (2x8),
// warp tile 64x32 (identical per-warp body to the validated R9 kernel),
// mma.m16n8k16 fp16 -> fp32. 512 thr x 128 regs = full regfile -> 1 CTA/SM,
// still 4 warps/SMSP. Fill traffic drops 25% vs the 128x128 variant.
// Smem rows 128 B (64 fp16); XOR swizzle on 16B chunks: chunk' = chunk ^ (row&7).
static constexpr int NCHUNK = IN_F / 64;               // 64
static constexpr uint32_t A_BYTES = 128 * 64 * 2;      // 16 KB
static constexpr uint32_t B_BYTES = 256 * 64 * 2;      // 32 KB
static constexpr uint32_t STAGE_BYTES = A_BYTES + B_BYTES;   // 48 KB
static constexpr uint32_t SMEM_BYTES = 3 * STAGE_BYTES;      // 144 KB

__device__ __forceinline__ void issue_stage(
    const __half* __restrict__ gA, const __half* __restrict__ gB,
    uint32_t sb, int kc, int s, int m0, int n0, int tid)
{
    const uint32_t stage = sb + (uint32_t)s * STAGE_BYTES;
    const int k0 = kc * 64;
#pragma unroll
    for (int i = 0; i < 2; ++i) {                      // A: 1024 16B chunks
        int id = tid + i * 512;
        int r = id >> 3, c = id & 7;
        const __half* src = gA + (size_t)(m0 + r) * IN_F + k0 + c * 8;
        uint32_t dst = stage + r * 128 + ((c ^ (r & 7)) * 16);
        cp_async16(dst, src);
    }
#pragma unroll
    for (int i = 0; i < 4; ++i) {                      // B: 2048 16B chunks
        int id = tid + i * 512;
        int r = id >> 3, c = id & 7;
        const __half* src = gB + (size_t)(n0 + r) * IN_F + k0 + c * 8;
        uint32_t dst = stage + A_BYTES + r * 128 + ((c ^ (r & 7)) * 16);
        cp_async16(dst, src);
    }
}

__global__ void __launch_bounds__(512, 1)
gemm_kernel(const float* __restrict__ bias, float* __restrict__ out)
{
    extern __shared__ char smem[];
    const uint32_t sb = smem_u32(smem);
    const int tid = threadIdx.x;
    const int lane = tid & 31;
    const int warp = tid >> 5;                // 0..15
    const int wm = warp >> 3;                 // 0..1 -> 64-row M slab
    const int wn = warp & 7;                  // 0..7 -> 32-col N slab
    const int n0 = blockIdx.x * 256;
    const int m0 = blockIdx.y * 128;
    const __half* gA = g_xh;
    const __half* gB = g_wh;

    // A ldmatrix: rows wm*64 + mt*16 + (lane&15); k sub-chunk = lane>>4
    const int rowA = wm * 64 + (lane & 15);
    const uint32_t aOff = (uint32_t)rowA * 128
                        + ((((lane >> 4) ^ (rowA & 7)) & 7) * 16);
    // B ldmatrix (paired x4 = two 8-wide n-tiles)
    const int rowB = wn * 32 + ((lane >> 4) << 3) + (lane & 7);
    const uint32_t cB = (uint32_t)((lane >> 3) & 1);
    const uint32_t bOff = (uint32_t)rowB * 128
                        + (((cB ^ (rowB & 7)) & 7) * 16);

    float acc[16][4];
#pragma unroll
    for (int i = 0; i < 16; ++i)
#pragma unroll
        for (int j = 0; j < 4; ++j) acc[i][j] = 0.0f;

    // prologue: stages 0,1
#pragma unroll
    for (int s = 0; s < 2; ++s) {
        issue_stage(gA, gB, sb, s, s, m0, n0, tid);
        cp_commit();
    }

    int s_comp = 0;   // stage holding chunk c
    int s_load = 2;   // stage to fill with chunk c+2
#pragma unroll 1
    for (int c = 0; c < NCHUNK; ++c) {
        cp_wait1();
        __syncthreads();
        if (c + 2 < NCHUNK)
            issue_stage(gA, gB, sb, c + 2, s_load, m0, n0, tid);
        cp_commit();

        const uint32_t stage = sb + (uint32_t)s_comp * STAGE_BYTES;
        const uint32_t aBase = stage + aOff;
        const uint32_t bBase = stage + A_BYTES + bOff;

#pragma unroll
        for (int ks = 0; ks < 4; ++ks) {
            const uint32_t kx = (uint32_t)ks << 5;
            uint32_t a[4][4];
#pragma unroll
            for (int mt = 0; mt < 4; ++mt)
                ldsm_x4(a[mt][0], a[mt][1], a[mt][2], a[mt][3],
                        (aBase + mt * 2048) ^ kx);
            uint32_t b[4][2];
            ldsm_x4(b[0][0], b[0][1], b[1][0], b[1][1], bBase ^ kx);
            ldsm_x4(b[2][0], b[2][1], b[3][0], b[3][1], (bBase + 2048) ^ kx);
#pragma unroll
            for (int mt = 0; mt < 4; ++mt)
#pragma unroll
                for (int nt = 0; nt < 4; ++nt)
                    mma16816(acc[mt * 4 + nt], a[mt], b[nt]);
        }
        s_comp = (s_comp == 2) ? 0 : s_comp + 1;
        s_load = (s_load == 2) ? 0 : s_load + 1;
    }

    // epilogue: add bias, store fp32
    const int r0 = m0 + wm * 64 + (lane >> 2);
    const int c0base = n0 + wn * 32 + 2 * (lane & 3);
#pragma unroll
    for (int nt = 0; nt < 4; ++nt) {
        const int col = c0base + nt * 8;
        const float b0 = __ldg(bias + col);
        const float b1 = __ldg(bias + col + 1);
#pragma unroll
        for (int mt = 0; mt < 4; ++mt) {
            const float* cc = acc[mt * 4 + nt];
            const int row = r0 + mt * 16;
            float2 v0 = { cc[0] + b0, cc[1] + b1 };
            float2 v1 = { cc[2] + b0, cc[3] + b1 };
            *reinterpret_cast<float2*>(out + (size_t)row * OUT_F + col) = v0;
            *reinterpret_cast<float2*>(out + (size_t)(row + 8) * OUT_F + col) = v1;
        }
    }
}

// ============================ host launcher ================================
extern "C" void kernel_launch(void* const* d_in, const int* in_sizes, int n_in,
                              void* d_out, int out_size) {
    (void)in_sizes; (void)n_in; (void)out_size;
    const float* x      = (const float*)d_in[0];
    const int*   packed = (const int*)  d_in[1];
    const float* alpha  = (const float*)d_in[2];
    const float* mu     = (const float*)d_in[3];
    const float* bias   = (const float*)d_in[4];
    const float* loraA  = (const float*)d_in[5];
    const float* loraB  = (const float*)d_in[6];
    float* out = (float*)d_out;

    cudaFuncSetAttribute(gemm_kernel, cudaFuncAttributeMaxDynamicSharedMemorySize,
                         SMEM_BYTES);

    prep_x_kernel<<<(TOKENS * (size_t)IN_F) / (256 * 8), 256>>>(x);
    dim3 wgrid(IN_F / 64, OUT_F / 64);       // (64, 64)
    build_w_kernel<<<wgrid, 256>>>(packed, alpha, mu, loraA, loraB);
    dim3 grid(OUT_F / 256, TOKENS / 128);    // (16, 64)
    gemm_kernel<<<grid, 512, SMEM_BYTES>>>(bias, out);
}

// round 13
// speedup vs baseline: 1.0563x; 1.0563x over previous
#include <cuda_runtime.h>
#include <cuda_fp16.h>
#include <cstdint>

// ============================ problem constants ============================
#define TOKENS 8192
#define IN_F   4096
#define OUT_F  4096
#define RANK   16

// ============================ scratch (device globals) =====================
__device__ __align__(1024) __half g_xh[(size_t)TOKENS * IN_F];  // x in fp16
__device__ __align__(1024) __half g_wh[(size_t)OUT_F * IN_F];   // fused W in fp16

// ============================ PTX helpers ==================================
__device__ __forceinline__ uint32_t smem_u32(const void* p) {
    uint32_t a;
    asm("{ .reg .u64 t; cvta.to.shared.u64 t, %1; cvt.u32.u64 %0, t; }" : "=r"(a) : "l"(p));
    return a;
}
__device__ __forceinline__ void cp_async16(uint32_t dst, const void* src) {
    asm volatile("cp.async.cg.shared.global [%0], [%1], 16;" :: "r"(dst), "l"(src) : "memory");
}
__device__ __forceinline__ void cp_commit() {
    asm volatile("cp.async.commit_group;" ::: "memory");
}
__device__ __forceinline__ void cp_wait1() {
    asm volatile("cp.async.wait_group 1;" ::: "memory");
}
__device__ __forceinline__ void ldsm_x4(uint32_t& r0, uint32_t& r1, uint32_t& r2, uint32_t& r3,
                                        uint32_t addr) {
    asm volatile("ldmatrix.sync.aligned.m8n8.x4.shared.b16 {%0,%1,%2,%3}, [%4];"
                 : "=r"(r0), "=r"(r1), "=r"(r2), "=r"(r3) : "r"(addr));
}
__device__ __forceinline__ void mma16816(float* c, const uint32_t* a, const uint32_t* b) {
    asm volatile(
        "mma.sync.aligned.m16n8k16.row.col.f32.f16.f16.f32 "
        "{%0,%1,%2,%3}, {%4,%5,%6,%7}, {%8,%9}, {%0,%1,%2,%3};"
        : "+f"(c[0]), "+f"(c[1]), "+f"(c[2]), "+f"(c[3])
        : "r"(a[0]), "r"(a[1]), "r"(a[2]), "r"(a[3]), "r"(b[0]), "r"(b[1]));
}

// =========== kernel 1 (fused prep): x->fp16  AND  W build, one launch ======
// Blocks [0, PREP_BLOCKS)            : convert x (fp32 -> fp16), 8 elems/thread
// Blocks [PREP_BLOCKS, PREP+WBLOCKS) : W = alpha*T + mu + lora_B@lora_A (fp16)
// The two phases touch disjoint data and run concurrently, hiding the W build
// (L2/ALU bound, ~8us) under the DRAM-bound x conversion (~27us).
static constexpr int PREP_BLOCKS = (TOKENS * IN_F) / (256 * 8);  // 16384
static constexpr int W_BLOCKS    = (IN_F / 64) * (OUT_F / 64);   // 4096

__global__ void __launch_bounds__(256) prep_fused_kernel(
    const float* __restrict__ x,
    const int*   __restrict__ packed,   // [OUT_F, 256]
    const float* __restrict__ alpha,    // [OUT_F]
    const float* __restrict__ mu,       // [OUT_F]
    const float* __restrict__ loraA,    // [RANK, IN_F]
    const float* __restrict__ loraB)    // [OUT_F, RANK]
{
    __shared__ float sA[RANK][64];
    __shared__ float sB[64][RANK];
    const int tid = threadIdx.x;

    if (blockIdx.x < PREP_BLOCKS) {
        // ---------------- phase A: x -> fp16 ----------------
        size_t base = ((size_t)blockIdx.x * 256 + tid) * 8;
        float4 v0 = *reinterpret_cast<const float4*>(x + base);
        float4 v1 = *reinterpret_cast<const float4*>(x + base + 4);
        __half2 h0 = __floats2half2_rn(v0.x, v0.y);
        __half2 h1 = __floats2half2_rn(v0.z, v0.w);
        __half2 h2 = __floats2half2_rn(v1.x, v1.y);
        __half2 h3 = __floats2half2_rn(v1.z, v1.w);
        uint4 o;
        o.x = reinterpret_cast<uint32_t&>(h0);
        o.y = reinterpret_cast<uint32_t&>(h1);
        o.z = reinterpret_cast<uint32_t&>(h2);
        o.w = reinterpret_cast<uint32_t&>(h3);
        *reinterpret_cast<uint4*>(&g_xh[base]) = o;
        return;
    }

    // ---------------- phase B: build W (64x64 tile) ----------------
    const int wb = blockIdx.x - PREP_BLOCKS;
    const int i0 = (wb & 63) * 64;            // input-col tile
    const int o0 = (wb >> 6) * 64;            // output-row tile

    for (int i = tid; i < RANK * 64; i += 256) {
        int r = i >> 6, j = i & 63;
        sA[r][j] = loraA[(size_t)r * IN_F + i0 + j];
    }
    for (int i = tid; i < 64 * RANK; i += 256) {
        int o = i >> 4, r = i & 15;
        sB[o][r] = loraB[(size_t)(o0 + o) * RANK + r];
    }
    __syncthreads();

    const int ol = tid >> 2;
    const int ig = tid & 3;
    const int o  = o0 + ol;
    const float a = alpha[o];
    const float m = mu[o];
    const int word = packed[(size_t)o * 256 + (i0 >> 4) + ig];

    float acc[16];
#pragma unroll
    for (int k = 0; k < 16; ++k)
        acc[k] = m + a * (float)(((word >> (2 * k)) & 3) - 1);

#pragma unroll
    for (int r = 0; r < RANK; ++r) {
        const float br = sB[ol][r];
        const float* arow = &sA[r][ig * 16];
#pragma unroll
        for (int k = 0; k < 16; ++k) acc[k] += br * arow[k];
    }

    __half2 hh[8];
#pragma unroll
    for (int k = 0; k < 8; ++k) hh[k] = __floats2half2_rn(acc[2 * k], acc[2 * k + 1]);
    uint4 u0, u1;
    u0.x = reinterpret_cast<uint32_t&>(hh[0]); u0.y = reinterpret_cast<uint32_t&>(hh[1]);
    u0.z = reinterpret_cast<uint32_t&>(hh[2]); u0.w = reinterpret_cast<uint32_t&>(hh[3]);
    u1.x = reinterpret_cast<uint32_t&>(hh[4]); u1.y = reinterpret_cast<uint32_t&>(hh[5]);
    u1.z = reinterpret_cast<uint32_t&>(hh[6]); u1.w = reinterpret_cast<uint32_t&>(hh[7]);
    __half* wrow = g_wh + (size_t)o * IN_F + i0 + ig * 16;
    *reinterpret_cast<uint4*>(wrow)     = u0;
    *reinterpret_cast<uint4*>(wrow + 8) = u1;
}

// ============================ kernel 2: GEMM (mma.sync HMMA) ===============
// Exact R9 configuration (validated 707us): CTA tile 128x128, BK=64, 3-stage
// cp.async pipeline, 8 warps (2x4), warp tile 64x32, mma.m16n8k16 fp16->fp32.
// __launch_bounds__(256,2) pins regs <=128 so 2 CTAs/SM (4 warps/SMSP).
// Smem rows 128 B (64 fp16); XOR swizzle on 16B chunks: chunk' = chunk ^ (row&7).
static constexpr int NCHUNK = IN_F / 64;              // 64
static constexpr uint32_t A_BYTES = 128 * 64 * 2;     // 16 KB
static constexpr uint32_t STAGE_BYTES = 2 * A_BYTES;  // 32 KB
static constexpr uint32_t SMEM_BYTES = 3 * STAGE_BYTES;  // 96 KB

__device__ __forceinline__ void issue_stage(
    const __half* __restrict__ gA, const __half* __restrict__ gB,
    uint32_t sb, int kc, int s, int m0, int n0, int tid)
{
    const uint32_t stage = sb + (uint32_t)s * STAGE_BYTES;
    const int k0 = kc * 64;
#pragma unroll
    for (int i = 0; i < 4; ++i) {                      // A: 1024 16B chunks
        int id = tid + i * 256;
        int r = id >> 3, c = id & 7;
        const __half* src = gA + (size_t)(m0 + r) * IN_F + k0 + c * 8;
        uint32_t dst = stage + r * 128 + ((c ^ (r & 7)) * 16);
        cp_async16(dst, src);
    }
#pragma unroll
    for (int i = 0; i < 4; ++i) {                      // B: 1024 16B chunks
        int id = tid + i * 256;
        int r = id >> 3, c = id & 7;
        const __half* src = gB + (size_t)(n0 + r) * IN_F + k0 + c * 8;
        uint32_t dst = stage + A_BYTES + r * 128 + ((c ^ (r & 7)) * 16);
        cp_async16(dst, src);
    }
}

__global__ void __launch_bounds__(256, 2)
gemm_kernel(const float* __restrict__ bias, float* __restrict__ out)
{
    extern __shared__ char smem[];
    const uint32_t sb = smem_u32(smem);
    const int tid = threadIdx.x;
    const int lane = tid & 31;
    const int warp = tid >> 5;
    const int wm = warp >> 2;                 // 0..1 -> 64-row M slab
    const int wn = warp & 3;                  // 0..3 -> 32-col N slab
    const int n0 = blockIdx.x * 128;
    const int m0 = blockIdx.y * 128;
    const __half* gA = g_xh;
    const __half* gB = g_wh;

    // A ldmatrix: rows wm*64 + mt*16 + (lane&15); k sub-chunk = lane>>4
    const int rowA = wm * 64 + (lane & 15);
    const uint32_t aOff = (uint32_t)rowA * 128
                        + ((((lane >> 4) ^ (rowA & 7)) & 7) * 16);
    // B ldmatrix (paired x4 = two 8-wide n-tiles)
    const int rowB = wn * 32 + ((lane >> 4) << 3) + (lane & 7);
    const uint32_t cB = (uint32_t)((lane >> 3) & 1);
    const uint32_t bOff = (uint32_t)rowB * 128
                        + (((cB ^ (rowB & 7)) & 7) * 16);

    float acc[16][4];
#pragma unroll
    for (int i = 0; i < 16; ++i)
#pragma unroll
        for (int j = 0; j < 4; ++j) acc[i][j] = 0.0f;

    // prologue: stages 0,1
#pragma unroll
    for (int s = 0; s < 2; ++s) {
        issue_stage(gA, gB, sb, s, s, m0, n0, tid);
        cp_commit();
    }

    int s_comp = 0;   // stage holding chunk c
    int s_load = 2;   // stage to fill with chunk c+2
#pragma unroll 1
    for (int c = 0; c < NCHUNK; ++c) {
        cp_wait1();
        __syncthreads();
        if (c + 2 < NCHUNK)
            issue_stage(gA, gB, sb, c + 2, s_load, m0, n0, tid);
        cp_commit();

        const uint32_t stage = sb + (uint32_t)s_comp * STAGE_BYTES;
        const uint32_t aBase = stage + aOff;
        const uint32_t bBase = stage + A_BYTES + bOff;

#pragma unroll
        for (int ks = 0; ks < 4; ++ks) {
            const uint32_t kx = (uint32_t)ks << 5;
            uint32_t a[4][4];
#pragma unroll
            for (int mt = 0; mt < 4; ++mt)
                ldsm_x4(a[mt][0], a[mt][1], a[mt][2], a[mt][3],
                        (aBase + mt * 2048) ^ kx);
            uint32_t b[4][2];
            ldsm_x4(b[0][0], b[0][1], b[1][0], b[1][1], bBase ^ kx);
            ldsm_x4(b[2][0], b[2][1], b[3][0], b[3][1], (bBase + 2048) ^ kx);
#pragma unroll
            for (int mt = 0; mt < 4; ++mt)
#pragma unroll
                for (int nt = 0; nt < 4; ++nt)
                    mma16816(acc[mt * 4 + nt], a[mt], b[nt]);
        }
        s_comp = (s_comp == 2) ? 0 : s_comp + 1;
        s_load = (s_load == 2) ? 0 : s_load + 1;
    }

    // epilogue: add bias, store fp32
    const int r0 = m0 + wm * 64 + (lane >> 2);
    const int c0base = n0 + wn * 32 + 2 * (lane & 3);
#pragma unroll
    for (int nt = 0; nt < 4; ++nt) {
        const int col = c0base + nt * 8;
        const float b0 = __ldg(bias + col);
        const float b1 = __ldg(bias + col + 1);
#pragma unroll
        for (int mt = 0; mt < 4; ++mt) {
            const float* cc = acc[mt * 4 + nt];
            const int row = r0 + mt * 16;
            float2 v0 = { cc[0] + b0, cc[1] + b1 };
            float2 v1 = { cc[2] + b0, cc[3] + b1 };
            *reinterpret_cast<float2*>(out + (size_t)row * OUT_F + col) = v0;
            *reinterpret_cast<float2*>(out + (size_t)(row + 8) * OUT_F + col) = v1;
        }
    }
}

// ============================ host launcher ================================
extern "C" void kernel_launch(void* const* d_in, const int* in_sizes, int n_in,
                              void* d_out, int out_size) {
    (void)in_sizes; (void)n_in; (void)out_size;
    const float* x      = (const float*)d_in[0];
    const int*   packed = (const int*)  d_in[1];
    const float* alpha  = (const float*)d_in[2];
    const float* mu     = (const float*)d_in[3];
    const float* bias   = (const float*)d_in[4];
    const float* loraA  = (const float*)d_in[5];
    const float* loraB  = (const float*)d_in[6];
    float* out = (float*)d_out;

    cudaFuncSetAttribute(gemm_kernel, cudaFuncAttributeMaxDynamicSharedMemorySize,
                         SMEM_BYTES);

    prep_fused_kernel<<<PREP_BLOCKS + W_BLOCKS, 256>>>(x, packed, alpha, mu,
                                                       loraA, loraB);
    dim3 grid(OUT_F / 128, TOKENS / 128);    // (32, 64)
    gemm_kernel<<<grid, 256, SMEM_BYTES>>>(bias, out);
}

// round 14
// speedup vs baseline: 1.0582x; 1.0018x over previous
#include <cuda_runtime.h>
#include <cuda_fp16.h>
#include <cstdint>

// ============================ problem constants ============================
#define TOKENS 8192
#define IN_F   4096
#define OUT_F  4096
#define RANK   16

// ============================ scratch (device globals) =====================
__device__ __align__(1024) __half g_xh[(size_t)TOKENS * IN_F];  // x in fp16
__device__ __align__(1024) __half g_wh[(size_t)OUT_F * IN_F];   // fused W in fp16

// ============================ PTX helpers ==================================
__device__ __forceinline__ uint32_t smem_u32(const void* p) {
    uint32_t a;
    asm("{ .reg .u64 t; cvta.to.shared.u64 t, %1; cvt.u32.u64 %0, t; }" : "=r"(a) : "l"(p));
    return a;
}
__device__ __forceinline__ void cp_async16(uint32_t dst, const void* src) {
    asm volatile("cp.async.cg.shared.global [%0], [%1], 16;" :: "r"(dst), "l"(src) : "memory");
}
__device__ __forceinline__ void cp_commit() {
    asm volatile("cp.async.commit_group;" ::: "memory");
}
__device__ __forceinline__ void cp_wait1() {
    asm volatile("cp.async.wait_group 1;" ::: "memory");
}
__device__ __forceinline__ void ldsm_x4(uint32_t& r0, uint32_t& r1, uint32_t& r2, uint32_t& r3,
                                        uint32_t addr) {
    asm volatile("ldmatrix.sync.aligned.m8n8.x4.shared.b16 {%0,%1,%2,%3}, [%4];"
                 : "=r"(r0), "=r"(r1), "=r"(r2), "=r"(r3) : "r"(addr));
}
__device__ __forceinline__ void mma16816(float* c, const uint32_t* a, const uint32_t* b) {
    asm volatile(
        "mma.sync.aligned.m16n8k16.row.col.f32.f16.f16.f32 "
        "{%0,%1,%2,%3}, {%4,%5,%6,%7}, {%8,%9}, {%0,%1,%2,%3};"
        : "+f"(c[0]), "+f"(c[1]), "+f"(c[2]), "+f"(c[3])
        : "r"(a[0]), "r"(a[1]), "r"(a[2]), "r"(a[3]), "r"(b[0]), "r"(b[1]));
}

// =========== kernel 1 (fused prep): x->fp16  AND  W build, one launch ======
static constexpr int PREP_BLOCKS = (TOKENS * IN_F) / (256 * 8);  // 16384
static constexpr int W_BLOCKS    = (IN_F / 64) * (OUT_F / 64);   // 4096

__global__ void __launch_bounds__(256) prep_fused_kernel(
    const float* __restrict__ x,
    const int*   __restrict__ packed,   // [OUT_F, 256]
    const float* __restrict__ alpha,    // [OUT_F]
    const float* __restrict__ mu,       // [OUT_F]
    const float* __restrict__ loraA,    // [RANK, IN_F]
    const float* __restrict__ loraB)    // [OUT_F, RANK]
{
    __shared__ float sA[RANK][64];
    __shared__ float sB[64][RANK];
    const int tid = threadIdx.x;

    if (blockIdx.x < PREP_BLOCKS) {
        // ---------------- phase A: x -> fp16 ----------------
        size_t base = ((size_t)blockIdx.x * 256 + tid) * 8;
        float4 v0 = *reinterpret_cast<const float4*>(x + base);
        float4 v1 = *reinterpret_cast<const float4*>(x + base + 4);
        __half2 h0 = __floats2half2_rn(v0.x, v0.y);
        __half2 h1 = __floats2half2_rn(v0.z, v0.w);
        __half2 h2 = __floats2half2_rn(v1.x, v1.y);
        __half2 h3 = __floats2half2_rn(v1.z, v1.w);
        uint4 o;
        o.x = reinterpret_cast<uint32_t&>(h0);
        o.y = reinterpret_cast<uint32_t&>(h1);
        o.z = reinterpret_cast<uint32_t&>(h2);
        o.w = reinterpret_cast<uint32_t&>(h3);
        *reinterpret_cast<uint4*>(&g_xh[base]) = o;
        return;
    }

    // ---------------- phase B: build W (64x64 tile) ----------------
    const int wb = blockIdx.x - PREP_BLOCKS;
    const int i0 = (wb & 63) * 64;            // input-col tile
    const int o0 = (wb >> 6) * 64;            // output-row tile

    for (int i = tid; i < RANK * 64; i += 256) {
        int r = i >> 6, j = i & 63;
        sA[r][j] = loraA[(size_t)r * IN_F + i0 + j];
    }
    for (int i = tid; i < 64 * RANK; i += 256) {
        int o = i >> 4, r = i & 15;
        sB[o][r] = loraB[(size_t)(o0 + o) * RANK + r];
    }
    __syncthreads();

    const int ol = tid >> 2;
    const int ig = tid & 3;
    const int o  = o0 + ol;
    const float a = alpha[o];
    const float m = mu[o];
    const int word = packed[(size_t)o * 256 + (i0 >> 4) + ig];

    float acc[16];
#pragma unroll
    for (int k = 0; k < 16; ++k)
        acc[k] = m + a * (float)(((word >> (2 * k)) & 3) - 1);

#pragma unroll
    for (int r = 0; r < RANK; ++r) {
        const float br = sB[ol][r];
        const float* arow = &sA[r][ig * 16];
#pragma unroll
        for (int k = 0; k < 16; ++k) acc[k] += br * arow[k];
    }

    __half2 hh[8];
#pragma unroll
    for (int k = 0; k < 8; ++k) hh[k] = __floats2half2_rn(acc[2 * k], acc[2 * k + 1]);
    uint4 u0, u1;
    u0.x = reinterpret_cast<uint32_t&>(hh[0]); u0.y = reinterpret_cast<uint32_t&>(hh[1]);
    u0.z = reinterpret_cast<uint32_t&>(hh[2]); u0.w = reinterpret_cast<uint32_t&>(hh[3]);
    u1.x = reinterpret_cast<uint32_t&>(hh[4]); u1.y = reinterpret_cast<uint32_t&>(hh[5]);
    u1.z = reinterpret_cast<uint32_t&>(hh[6]); u1.w = reinterpret_cast<uint32_t&>(hh[7]);
    __half* wrow = g_wh + (size_t)o * IN_F + i0 + ig * 16;
    *reinterpret_cast<uint4*>(wrow)     = u0;
    *reinterpret_cast<uint4*>(wrow + 8) = u1;
}

// ============================ kernel 2: GEMM (mma.sync HMMA) ===============
// R13: CTA tile 128x128, BK=64, 3-stage cp.async pipeline, FOUR warps (2x2),
// warp tile 64x64, mma.m16n8k16 fp16 -> fp32. 128 thr/CTA, 2 CTAs/SM.
// ldsm-per-HMMA drops 0.375 -> 0.25 (smem reads 12.6 -> 8.4 GB) while keeping
// small barrier groups + 2 independent CTAs per SM.
// Smem rows 128 B (64 fp16); XOR swizzle on 16B chunks: chunk' = chunk ^ (row&7).
static constexpr int NCHUNK = IN_F / 64;              // 64
static constexpr uint32_t A_BYTES = 128 * 64 * 2;     // 16 KB
static constexpr uint32_t STAGE_BYTES = 2 * A_BYTES;  // 32 KB
static constexpr uint32_t SMEM_BYTES = 3 * STAGE_BYTES;  // 96 KB

__device__ __forceinline__ void issue_stage(
    const __half* __restrict__ gA, const __half* __restrict__ gB,
    uint32_t sb, int kc, int s, int m0, int n0, int tid)
{
    const uint32_t stage = sb + (uint32_t)s * STAGE_BYTES;
    const int k0 = kc * 64;
#pragma unroll
    for (int i = 0; i < 8; ++i) {                      // A: 1024 16B chunks
        int id = tid + i * 128;
        int r = id >> 3, c = id & 7;
        const __half* src = gA + (size_t)(m0 + r) * IN_F + k0 + c * 8;
        uint32_t dst = stage + r * 128 + ((c ^ (r & 7)) * 16);
        cp_async16(dst, src);
    }
#pragma unroll
    for (int i = 0; i < 8; ++i) {                      // B: 1024 16B chunks
        int id = tid + i * 128;
        int r = id >> 3, c = id & 7;
        const __half* src = gB + (size_t)(n0 + r) * IN_F + k0 + c * 8;
        uint32_t dst = stage + A_BYTES + r * 128 + ((c ^ (r & 7)) * 16);
        cp_async16(dst, src);
    }
}

__global__ void __launch_bounds__(128, 2)
gemm_kernel(const float* __restrict__ bias, float* __restrict__ out)
{
    extern __shared__ char smem[];
    const uint32_t sb = smem_u32(smem);
    const int tid = threadIdx.x;
    const int lane = tid & 31;
    const int warp = tid >> 5;                // 0..3
    const int wm = warp >> 1;                 // 0..1 -> 64-row M slab
    const int wn = warp & 1;                  // 0..1 -> 64-col N slab
    const int n0 = blockIdx.x * 128;
    const int m0 = blockIdx.y * 128;
    const __half* gA = g_xh;
    const __half* gB = g_wh;

    // A ldmatrix: rows wm*64 + mt*16 + (lane&15); k sub-chunk = lane>>4
    const int rowA = wm * 64 + (lane & 15);
    const uint32_t aOff = (uint32_t)rowA * 128
                        + ((((lane >> 4) ^ (rowA & 7)) & 7) * 16);
    // B ldmatrix (paired x4 = two 8-wide n-tiles per load, 4 loads = 64 cols)
    // lanes 0-7: n(+0..7) k-lo, 8-15: k-hi, 16-23: n(+8..15) k-lo, 24-31: k-hi
    const int rowB = wn * 64 + ((lane >> 4) << 3) + (lane & 7);
    const uint32_t cB = (uint32_t)((lane >> 3) & 1);
    const uint32_t bOff = (uint32_t)rowB * 128
                        + (((cB ^ (rowB & 7)) & 7) * 16);
    // +16-row steps keep (row & 7) invariant -> fixed +2048B per n-tile pair.

    float acc[32][4];                          // [mt*8+nt][4]
#pragma unroll
    for (int i = 0; i < 32; ++i)
#pragma unroll
        for (int j = 0; j < 4; ++j) acc[i][j] = 0.0f;

    // prologue: stages 0,1
#pragma unroll
    for (int s = 0; s < 2; ++s) {
        issue_stage(gA, gB, sb, s, s, m0, n0, tid);
        cp_commit();
    }

    int s_comp = 0;   // stage holding chunk c
    int s_load = 2;   // stage to fill with chunk c+2
#pragma unroll 1
    for (int c = 0; c < NCHUNK; ++c) {
        cp_wait1();
        __syncthreads();
        if (c + 2 < NCHUNK)
            issue_stage(gA, gB, sb, c + 2, s_load, m0, n0, tid);
        cp_commit();

        const uint32_t stage = sb + (uint32_t)s_comp * STAGE_BYTES;
        const uint32_t aBase = stage + aOff;
        const uint32_t bBase = stage + A_BYTES + bOff;

#pragma unroll
        for (int ks = 0; ks < 4; ++ks) {
            const uint32_t kx = (uint32_t)ks << 5;
            uint32_t a[4][4];
#pragma unroll
            for (int mt = 0; mt < 4; ++mt)
                ldsm_x4(a[mt][0], a[mt][1], a[mt][2], a[mt][3],
                        (aBase + mt * 2048) ^ kx);
            uint32_t b[8][2];
#pragma unroll
            for (int p = 0; p < 4; ++p)
                ldsm_x4(b[2 * p][0], b[2 * p][1], b[2 * p + 1][0], b[2 * p + 1][1],
                        (bBase + p * 2048) ^ kx);
#pragma unroll
            for (int mt = 0; mt < 4; ++mt)
#pragma unroll
                for (int nt = 0; nt < 8; ++nt)
                    mma16816(acc[mt * 8 + nt], a[mt], b[nt]);
        }
        s_comp = (s_comp == 2) ? 0 : s_comp + 1;
        s_load = (s_load == 2) ? 0 : s_load + 1;
    }

    // epilogue: add bias, store fp32
    const int r0 = m0 + wm * 64 + (lane >> 2);
    const int c0base = n0 + wn * 64 + 2 * (lane & 3);
#pragma unroll
    for (int nt = 0; nt < 8; ++nt) {
        const int col = c0base + nt * 8;
        const float b0 = __ldg(bias + col);
        const float b1 = __ldg(bias + col + 1);
#pragma unroll
        for (int mt = 0; mt < 4; ++mt) {
            const float* cc = acc[mt * 8 + nt];
            const int row = r0 + mt * 16;
            float2 v0 = { cc[0] + b0, cc[1] + b1 };
            float2 v1 = { cc[2] + b0, cc[3] + b1 };
            *reinterpret_cast<float2*>(out + (size_t)row * OUT_F + col) = v0;
            *reinterpret_cast<float2*>(out + (size_t)(row + 8) * OUT_F + col) = v1;
        }
    }
}

// ============================ host launcher ================================
extern "C" void kernel_launch(void* const* d_in, const int* in_sizes, int n_in,
                              void* d_out, int out_size) {
    (void)in_sizes; (void)n_in; (void)out_size;
    const float* x      = (const float*)d_in[0];
    const int*   packed = (const int*)  d_in[1];
    const float* alpha  = (const float*)d_in[2];
    const float* mu     = (const float*)d_in[3];
    const float* bias   = (const float*)d_in[4];
    const float* loraA  = (const float*)d_in[5];
    const float* loraB  = (const float*)d_in[6];
    float* out = (float*)d_out;

    cudaFuncSetAttribute(gemm_kernel, cudaFuncAttributeMaxDynamicSharedMemorySize,
                         SMEM_BYTES);

    prep_fused_kernel<<<PREP_BLOCKS + W_BLOCKS, 256>>>(x, packed, alpha, mu,
                                                       loraA, loraB);
    dim3 grid(OUT_F / 128, TOKENS / 128);    // (32, 64)
    gemm_kernel<<<grid, 128, SMEM_BYTES>>>(bias, out);
}

// round 16
// speedup vs baseline: 1.1327x; 1.0705x over previous
#include <cuda_runtime.h>
#include <cuda_fp16.h>
#include <cstdint>

// ============================ problem constants ============================
#define TOKENS 8192
#define IN_F   4096
#define OUT_F  4096
#define RANK   16

// ============================ scratch (device globals) =====================
__device__ __align__(1024) __half g_xh[(size_t)TOKENS * IN_F];  // x in fp16
__device__ __align__(1024) __half g_wh[(size_t)OUT_F * IN_F];   // fused W in fp16

// ============================ PTX helpers ==================================
__device__ __forceinline__ uint32_t smem_u32(const void* p) {
    uint32_t a;
    asm("{ .reg .u64 t; cvta.to.shared.u64 t, %1; cvt.u32.u64 %0, t; }" : "=r"(a) : "l"(p));
    return a;
}
__device__ __forceinline__ void cp_async16(uint32_t dst, const void* src) {
    asm volatile("cp.async.cg.shared.global [%0], [%1], 16;" :: "r"(dst), "l"(src) : "memory");
}
__device__ __forceinline__ void ldsm_x4(uint32_t& r0, uint32_t& r1, uint32_t& r2, uint32_t& r3,
                                        uint32_t addr) {
    asm volatile("ldmatrix.sync.aligned.m8n8.x4.shared.b16 {%0,%1,%2,%3}, [%4];"
                 : "=r"(r0), "=r"(r1), "=r"(r2), "=r"(r3) : "r"(addr));
}
__device__ __forceinline__ void mma16816(float* c, const uint32_t* a, const uint32_t* b) {
    asm volatile(
        "mma.sync.aligned.m16n8k16.row.col.f32.f16.f16.f32 "
        "{%0,%1,%2,%3}, {%4,%5,%6,%7}, {%8,%9}, {%0,%1,%2,%3};"
        : "+f"(c[0]), "+f"(c[1]), "+f"(c[2]), "+f"(c[3])
        : "r"(a[0]), "r"(a[1]), "r"(a[2]), "r"(a[3]), "r"(b[0]), "r"(b[1]));
}
// ---- mbarrier (sm_90 baseline ops; valid on sm_103 base target) ----
__device__ __forceinline__ void mbar_init(uint32_t a, uint32_t cnt) {
    asm volatile("mbarrier.init.shared::cta.b64 [%0], %1;" :: "r"(a), "r"(cnt) : "memory");
}
__device__ __forceinline__ void mbar_arrive(uint32_t a) {
    asm volatile("mbarrier.arrive.shared::cta.b64 _, [%0];" :: "r"(a) : "memory");
}
// NOTE: .noinc is load-bearing. The default variant increments the barrier's
// expected-arrival count at issue; with init count == thread count that
// inflates the expectation and the barrier never flips (R14 deadlock).
__device__ __forceinline__ void cp_async_arrive_noinc(uint32_t a) {
    asm volatile("cp.async.mbarrier.arrive.noinc.shared::cta.b64 [%0];" :: "r"(a) : "memory");
}
__device__ __forceinline__ void mbar_wait(uint32_t a, uint32_t parity) {
    uint32_t done;
    asm volatile(
        "{\n\t.reg .pred p;\n\t"
        "mbarrier.try_wait.parity.acquire.cta.shared::cta.b64 p, [%1], %2;\n\t"
        "selp.b32 %0, 1, 0, p;\n\t}"
        : "=r"(done) : "r"(a), "r"(parity) : "memory");
    if (!done) {
        asm volatile(
            "{\n\t.reg .pred P1;\n"
            "W_%=:\n\t"
            "mbarrier.try_wait.parity.acquire.cta.shared::cta.b64 P1, [%0], %1, 0x989680;\n\t"
            "@!P1 bra W_%=;\n\t}"
            :: "r"(a), "r"(parity) : "memory");
    }
}

// =========== kernel 1 (fused prep): x->fp16  AND  W build, one launch ======
static constexpr int PREP_BLOCKS = (TOKENS * IN_F) / (256 * 8);  // 16384
static constexpr int W_BLOCKS    = (IN_F / 64) * (OUT_F / 64);   // 4096

__global__ void __launch_bounds__(256) prep_fused_kernel(
    const float* __restrict__ x,
    const int*   __restrict__ packed,   // [OUT_F, 256]
    const float* __restrict__ alpha,    // [OUT_F]
    const float* __restrict__ mu,       // [OUT_F]
    const float* __restrict__ loraA,    // [RANK, IN_F]
    const float* __restrict__ loraB)    // [OUT_F, RANK]
{
    __shared__ float sA[RANK][64];
    __shared__ float sB[64][RANK];
    const int tid = threadIdx.x;

    if (blockIdx.x < PREP_BLOCKS) {
        // ---------------- phase A: x -> fp16 ----------------
        size_t base = ((size_t)blockIdx.x * 256 + tid) * 8;
        float4 v0 = *reinterpret_cast<const float4*>(x + base);
        float4 v1 = *reinterpret_cast<const float4*>(x + base + 4);
        __half2 h0 = __floats2half2_rn(v0.x, v0.y);
        __half2 h1 = __floats2half2_rn(v0.z, v0.w);
        __half2 h2 = __floats2half2_rn(v1.x, v1.y);
        __half2 h3 = __floats2half2_rn(v1.z, v1.w);
        uint4 o;
        o.x = reinterpret_cast<uint32_t&>(h0);
        o.y = reinterpret_cast<uint32_t&>(h1);
        o.z = reinterpret_cast<uint32_t&>(h2);
        o.w = reinterpret_cast<uint32_t&>(h3);
        *reinterpret_cast<uint4*>(&g_xh[base]) = o;
        return;
    }

    // ---------------- phase B: build W (64x64 tile) ----------------
    const int wb = blockIdx.x - PREP_BLOCKS;
    const int i0 = (wb & 63) * 64;            // input-col tile
    const int o0 = (wb >> 6) * 64;            // output-row tile

    for (int i = tid; i < RANK * 64; i += 256) {
        int r = i >> 6, j = i & 63;
        sA[r][j] = loraA[(size_t)r * IN_F + i0 + j];
    }
    for (int i = tid; i < 64 * RANK; i += 256) {
        int o = i >> 4, r = i & 15;
        sB[o][r] = loraB[(size_t)(o0 + o) * RANK + r];
    }
    __syncthreads();

    const int ol = tid >> 2;
    const int ig = tid & 3;
    const int o  = o0 + ol;
    const float a = alpha[o];
    const float m = mu[o];
    const int word = packed[(size_t)o * 256 + (i0 >> 4) + ig];

    float acc[16];
#pragma unroll
    for (int k = 0; k < 16; ++k)
        acc[k] = m + a * (float)(((word >> (2 * k)) & 3) - 1);

#pragma unroll
    for (int r = 0; r < RANK; ++r) {
        const float br = sB[ol][r];
        const float* arow = &sA[r][ig * 16];
#pragma unroll
        for (int k = 0; k < 16; ++k) acc[k] += br * arow[k];
    }

    __half2 hh[8];
#pragma unroll
    for (int k = 0; k < 8; ++k) hh[k] = __floats2half2_rn(acc[2 * k], acc[2 * k + 1]);
    uint4 u0, u1;
    u0.x = reinterpret_cast<uint32_t&>(hh[0]); u0.y = reinterpret_cast<uint32_t&>(hh[1]);
    u0.z = reinterpret_cast<uint32_t&>(hh[2]); u0.w = reinterpret_cast<uint32_t&>(hh[3]);
    u1.x = reinterpret_cast<uint32_t&>(hh[4]); u1.y = reinterpret_cast<uint32_t&>(hh[5]);
    u1.z = reinterpret_cast<uint32_t&>(hh[6]); u1.w = reinterpret_cast<uint32_t&>(hh[7]);
    __half* wrow = g_wh + (size_t)o * IN_F + i0 + ig * 16;
    *reinterpret_cast<uint4*>(wrow)     = u0;
    *reinterpret_cast<uint4*>(wrow + 8) = u1;
}

// ============================ kernel 2: GEMM (mma.sync HMMA) ===============
// R15 = R14 with the .noinc fix: CTA 128x128, warp tile 64x64, BK=64,
// 3-stage ring, 128 thr/CTA, 2 CTAs/SM. Per-stage mbarriers instead of
// full-CTA __syncthreads:
//   full[s] (count 128): cp.async.mbarrier.arrive.noinc per thread
//   free[s] (count 4):   lane 0 of each warp arrives after its ldsm reads
// Warps proceed independently (skew bounded by the ring), keeping the
// tensor pipe fed across chunk boundaries.
static constexpr int NCHUNK = IN_F / 64;              // 64
static constexpr uint32_t A_BYTES = 128 * 64 * 2;     // 16 KB
static constexpr uint32_t STAGE_BYTES = 2 * A_BYTES;  // 32 KB
static constexpr uint32_t BAR_OFF = 3 * STAGE_BYTES;  // 96 KB
static constexpr uint32_t SMEM_BYTES = BAR_OFF + 64;  // + barrier block

#define FULL_BAR(sb, s) ((sb) + BAR_OFF + (uint32_t)(s) * 16)
#define FREE_BAR(sb, s) ((sb) + BAR_OFF + (uint32_t)(s) * 16 + 8)

__device__ __forceinline__ void issue_stage(
    const __half* __restrict__ gA, const __half* __restrict__ gB,
    uint32_t sb, int kc, int s, int m0, int n0, int tid)
{
    const uint32_t stage = sb + (uint32_t)s * STAGE_BYTES;
    const int k0 = kc * 64;
#pragma unroll
    for (int i = 0; i < 8; ++i) {                      // A: 1024 16B chunks
        int id = tid + i * 128;
        int r = id >> 3, c = id & 7;
        const __half* src = gA + (size_t)(m0 + r) * IN_F + k0 + c * 8;
        uint32_t dst = stage + r * 128 + ((c ^ (r & 7)) * 16);
        cp_async16(dst, src);
    }
#pragma unroll
    for (int i = 0; i < 8; ++i) {                      // B: 1024 16B chunks
        int id = tid + i * 128;
        int r = id >> 3, c = id & 7;
        const __half* src = gB + (size_t)(n0 + r) * IN_F + k0 + c * 8;
        uint32_t dst = stage + A_BYTES + r * 128 + ((c ^ (r & 7)) * 16);
        cp_async16(dst, src);
    }
}

__global__ void __launch_bounds__(128, 2)
gemm_kernel(const float* __restrict__ bias, float* __restrict__ out)
{
    extern __shared__ char smem[];
    const uint32_t sb = smem_u32(smem);
    const int tid = threadIdx.x;
    const int lane = tid & 31;
    const int warp = tid >> 5;                // 0..3
    const int wm = warp >> 1;                 // 0..1 -> 64-row M slab
    const int wn = warp & 1;                  // 0..1 -> 64-col N slab
    const int n0 = blockIdx.x * 128;
    const int m0 = blockIdx.y * 128;
    const __half* gA = g_xh;
    const __half* gB = g_wh;

    // barriers
    if (tid == 0) {
#pragma unroll
        for (int s = 0; s < 3; ++s) {
            mbar_init(FULL_BAR(sb, s), 128);
            mbar_init(FREE_BAR(sb, s), 4);
        }
    }
    __syncthreads();

    // A ldmatrix: rows wm*64 + mt*16 + (lane&15); k sub-chunk = lane>>4
    const int rowA = wm * 64 + (lane & 15);
    const uint32_t aOff = (uint32_t)rowA * 128
                        + ((((lane >> 4) ^ (rowA & 7)) & 7) * 16);
    // B ldmatrix (paired x4 = two 8-wide n-tiles per load, 4 loads = 64 cols)
    const int rowB = wn * 64 + ((lane >> 4) << 3) + (lane & 7);
    const uint32_t cB = (uint32_t)((lane >> 3) & 1);
    const uint32_t bOff = (uint32_t)rowB * 128
                        + (((cB ^ (rowB & 7)) & 7) * 16);

    float acc[32][4];                          // [mt*8+nt][4]
#pragma unroll
    for (int i = 0; i < 32; ++i)
#pragma unroll
        for (int j = 0; j < 4; ++j) acc[i][j] = 0.0f;

    // prologue: fill stages 0,1 (first lap — no free-wait needed)
    issue_stage(gA, gB, sb, 0, 0, m0, n0, tid);
    cp_async_arrive_noinc(FULL_BAR(sb, 0));
    issue_stage(gA, gB, sb, 1, 1, m0, n0, tid);
    cp_async_arrive_noinc(FULL_BAR(sb, 1));

    int ps = 2, pp = 1;   // producer cursor; phase 1 -> first-lap waits pass
    int cs = 0, cph = 0;  // consumer cursor

#pragma unroll 1
    for (int c = 0; c < NCHUNK; ++c) {
        // ---- producer: fill chunk c+2 into stage ps (WAR-protected) ----
        if (c + 2 < NCHUNK) {
            mbar_wait(FREE_BAR(sb, ps), (uint32_t)pp);
            issue_stage(gA, gB, sb, c + 2, ps, m0, n0, tid);
            cp_async_arrive_noinc(FULL_BAR(sb, ps));
            if (++ps == 3) { ps = 0; pp ^= 1; }
        }

        // ---- consumer: wait chunk c ready, compute ----
        mbar_wait(FULL_BAR(sb, cs), (uint32_t)cph);
        const uint32_t stage = sb + (uint32_t)cs * STAGE_BYTES;
        const uint32_t aBase = stage + aOff;
        const uint32_t bBase = stage + A_BYTES + bOff;

#pragma unroll
        for (int ks = 0; ks < 4; ++ks) {
            const uint32_t kx = (uint32_t)ks << 5;
            uint32_t a[4][4];
#pragma unroll
            for (int mt = 0; mt < 4; ++mt)
                ldsm_x4(a[mt][0], a[mt][1], a[mt][2], a[mt][3],
                        (aBase + mt * 2048) ^ kx);
            uint32_t b[8][2];
#pragma unroll
            for (int p = 0; p < 4; ++p)
                ldsm_x4(b[2 * p][0], b[2 * p][1], b[2 * p + 1][0], b[2 * p + 1][1],
                        (bBase + p * 2048) ^ kx);
#pragma unroll
            for (int mt = 0; mt < 4; ++mt)
#pragma unroll
                for (int nt = 0; nt < 8; ++nt)
                    mma16816(acc[mt * 8 + nt], a[mt], b[nt]);
        }
        // all smem reads of stage cs done (ldsm is synchronous) -> free it
        if (lane == 0) mbar_arrive(FREE_BAR(sb, cs));
        if (++cs == 3) { cs = 0; cph ^= 1; }
    }

    // epilogue: add bias, store fp32
    const int r0 = m0 + wm * 64 + (lane >> 2);
    const int c0base = n0 + wn * 64 + 2 * (lane & 3);
#pragma unroll
    for (int nt = 0; nt < 8; ++nt) {
        const int col = c0base + nt * 8;
        const float b0 = __ldg(bias + col);
        const float b1 = __ldg(bias + col + 1);
#pragma unroll
        for (int mt = 0; mt < 4; ++mt) {
            const float* cc = acc[mt * 8 + nt];
            const int row = r0 + mt * 16;
            float2 v0 = { cc[0] + b0, cc[1] + b1 };
            float2 v1 = { cc[2] + b0, cc[3] + b1 };
            *reinterpret_cast<float2*>(out + (size_t)row * OUT_F + col) = v0;
            *reinterpret_cast<float2*>(out + (size_t)(row + 8) * OUT_F + col) = v1;
        }
    }
}

// ============================ host launcher ================================
extern "C" void kernel_launch(void* const* d_in, const int* in_sizes, int n_in,
                              void* d_out, int out_size) {
    (void)in_sizes; (void)n_in; (void)out_size;
    const float* x      = (const float*)d_in[0];
    const int*   packed = (const int*)  d_in[1];
    const float* alpha  = (const float*)d_in[2];
    const float* mu     = (const float*)d_in[3];
    const float* bias   = (const float*)d_in[4];
    const float* loraA  = (const float*)d_in[5];
    const float* loraB  = (const float*)d_in[6];
    float* out = (float*)d_out;

    cudaFuncSetAttribute(gemm_kernel, cudaFuncAttributeMaxDynamicSharedMemorySize,
                         SMEM_BYTES);

    prep_fused_kernel<<<PREP_BLOCKS + W_BLOCKS, 256>>>(x, packed, alpha, mu,
                                                       loraA, loraB);
    dim3 grid(OUT_F / 128, TOKENS / 128);    // (32, 64)
    gemm_kernel<<<grid, 128, SMEM_BYTES>>>(bias, out);
}

// round 17
// speedup vs baseline: 1.1352x; 1.0021x over previous
#include <cuda_runtime.h>
#include <cuda_fp16.h>
#include <cstdint>

// ============================ problem constants ============================
#define TOKENS 8192
#define IN_F   4096
#define OUT_F  4096
#define RANK   16

// ============================ scratch (device globals) =====================
__device__ __align__(1024) __half g_xh[(size_t)TOKENS * IN_F];  // x in fp16
__device__ __align__(1024) __half g_wh[(size_t)OUT_F * IN_F];   // fused W in fp16

// ============================ PTX helpers ==================================
__device__ __forceinline__ uint32_t smem_u32(const void* p) {
    uint32_t a;
    asm("{ .reg .u64 t; cvta.to.shared.u64 t, %1; cvt.u32.u64 %0, t; }" : "=r"(a) : "l"(p));
    return a;
}
__device__ __forceinline__ void cp_async16(uint32_t dst, const void* src) {
    asm volatile("cp.async.cg.shared.global [%0], [%1], 16;" :: "r"(dst), "l"(src) : "memory");
}
__device__ __forceinline__ void ldsm_x4(uint32_t& r0, uint32_t& r1, uint32_t& r2, uint32_t& r3,
                                        uint32_t addr) {
    asm volatile("ldmatrix.sync.aligned.m8n8.x4.shared.b16 {%0,%1,%2,%3}, [%4];"
                 : "=r"(r0), "=r"(r1), "=r"(r2), "=r"(r3) : "r"(addr));
}
__device__ __forceinline__ void mma16816(float* c, const uint32_t* a, const uint32_t* b) {
    asm volatile(
        "mma.sync.aligned.m16n8k16.row.col.f32.f16.f16.f32 "
        "{%0,%1,%2,%3}, {%4,%5,%6,%7}, {%8,%9}, {%0,%1,%2,%3};"
        : "+f"(c[0]), "+f"(c[1]), "+f"(c[2]), "+f"(c[3])
        : "r"(a[0]), "r"(a[1]), "r"(a[2]), "r"(a[3]), "r"(b[0]), "r"(b[1]));
}
// ---- mbarrier (sm_90 baseline ops; valid on sm_103 base target) ----
__device__ __forceinline__ void mbar_init(uint32_t a, uint32_t cnt) {
    asm volatile("mbarrier.init.shared::cta.b64 [%0], %1;" :: "r"(a), "r"(cnt) : "memory");
}
__device__ __forceinline__ void mbar_arrive(uint32_t a) {
    asm volatile("mbarrier.arrive.shared::cta.b64 _, [%0];" :: "r"(a) : "memory");
}
// .noinc is load-bearing (R14 deadlock: default variant inflates the count).
__device__ __forceinline__ void cp_async_arrive_noinc(uint32_t a) {
    asm volatile("cp.async.mbarrier.arrive.noinc.shared::cta.b64 [%0];" :: "r"(a) : "memory");
}
__device__ __forceinline__ void mbar_wait(uint32_t a, uint32_t parity) {
    uint32_t done;
    asm volatile(
        "{\n\t.reg .pred p;\n\t"
        "mbarrier.try_wait.parity.acquire.cta.shared::cta.b64 p, [%1], %2;\n\t"
        "selp.b32 %0, 1, 0, p;\n\t}"
        : "=r"(done) : "r"(a), "r"(parity) : "memory");
    if (!done) {
        asm volatile(
            "{\n\t.reg .pred P1;\n"
            "W_%=:\n\t"
            "mbarrier.try_wait.parity.acquire.cta.shared::cta.b64 P1, [%0], %1, 0x989680;\n\t"
            "@!P1 bra W_%=;\n\t}"
            :: "r"(a), "r"(parity) : "memory");
    }
}

// =========== kernel 1 (fused prep): x->fp16  AND  W build, one launch ======
static constexpr int PREP_BLOCKS = (TOKENS * IN_F) / (256 * 8);  // 16384
static constexpr int W_BLOCKS    = (IN_F / 64) * (OUT_F / 64);   // 4096

__global__ void __launch_bounds__(256) prep_fused_kernel(
    const float* __restrict__ x,
    const int*   __restrict__ packed,   // [OUT_F, 256]
    const float* __restrict__ alpha,    // [OUT_F]
    const float* __restrict__ mu,       // [OUT_F]
    const float* __restrict__ loraA,    // [RANK, IN_F]
    const float* __restrict__ loraB)    // [OUT_F, RANK]
{
    __shared__ float sA[RANK][64];
    __shared__ float sB[64][RANK];
    const int tid = threadIdx.x;

    if (blockIdx.x < PREP_BLOCKS) {
        // ---------------- phase A: x -> fp16 ----------------
        size_t base = ((size_t)blockIdx.x * 256 + tid) * 8;
        float4 v0 = *reinterpret_cast<const float4*>(x + base);
        float4 v1 = *reinterpret_cast<const float4*>(x + base + 4);
        __half2 h0 = __floats2half2_rn(v0.x, v0.y);
        __half2 h1 = __floats2half2_rn(v0.z, v0.w);
        __half2 h2 = __floats2half2_rn(v1.x, v1.y);
        __half2 h3 = __floats2half2_rn(v1.z, v1.w);
        uint4 o;
        o.x = reinterpret_cast<uint32_t&>(h0);
        o.y = reinterpret_cast<uint32_t&>(h1);
        o.z = reinterpret_cast<uint32_t&>(h2);
        o.w = reinterpret_cast<uint32_t&>(h3);
        *reinterpret_cast<uint4*>(&g_xh[base]) = o;
        return;
    }

    // ---------------- phase B: build W (64x64 tile) ----------------
    const int wb = blockIdx.x - PREP_BLOCKS;
    const int i0 = (wb & 63) * 64;            // input-col tile
    const int o0 = (wb >> 6) * 64;            // output-row tile

    for (int i = tid; i < RANK * 64; i += 256) {
        int r = i >> 6, j = i & 63;
        sA[r][j] = loraA[(size_t)r * IN_F + i0 + j];
    }
    for (int i = tid; i < 64 * RANK; i += 256) {
        int o = i >> 4, r = i & 15;
        sB[o][r] = loraB[(size_t)(o0 + o) * RANK + r];
    }
    __syncthreads();

    const int ol = tid >> 2;
    const int ig = tid & 3;
    const int o  = o0 + ol;
    const float a = alpha[o];
    const float m = mu[o];
    const int word = packed[(size_t)o * 256 + (i0 >> 4) + ig];

    float acc[16];
#pragma unroll
    for (int k = 0; k < 16; ++k)
        acc[k] = m + a * (float)(((word >> (2 * k)) & 3) - 1);

#pragma unroll
    for (int r = 0; r < RANK; ++r) {
        const float br = sB[ol][r];
        const float* arow = &sA[r][ig * 16];
#pragma unroll
        for (int k = 0; k < 16; ++k) acc[k] += br * arow[k];
    }

    __half2 hh[8];
#pragma unroll
    for (int k = 0; k < 8; ++k) hh[k] = __floats2half2_rn(acc[2 * k], acc[2 * k + 1]);
    uint4 u0, u1;
    u0.x = reinterpret_cast<uint32_t&>(hh[0]); u0.y = reinterpret_cast<uint32_t&>(hh[1]);
    u0.z = reinterpret_cast<uint32_t&>(hh[2]); u0.w = reinterpret_cast<uint32_t&>(hh[3]);
    u1.x = reinterpret_cast<uint32_t&>(hh[4]); u1.y = reinterpret_cast<uint32_t&>(hh[5]);
    u1.z = reinterpret_cast<uint32_t&>(hh[6]); u1.w = reinterpret_cast<uint32_t&>(hh[7]);
    __half* wrow = g_wh + (size_t)o * IN_F + i0 + ig * 16;
    *reinterpret_cast<uint4*>(wrow)     = u0;
    *reinterpret_cast<uint4*>(wrow + 8) = u1;
}

// ============================ kernel 2: GEMM (mma.sync HMMA) ===============
// R16 = R15 resequenced: CTA 128x128, warp tile 64x64, BK=64, 3-stage ring,
// per-stage mbarriers, 128 thr/CTA, 2 CTAs/SM.
//   - producer stint (wait_free + 16 cp.async) moved AFTER the ks=0 ldsm so
//     the warp holds ready fragments across the wait window
//   - free[cs] arrive moved to right after the ks=3 ldsm (last smem read),
//     giving producers ~1 mma-block more slack
static constexpr int NCHUNK = IN_F / 64;              // 64
static constexpr uint32_t A_BYTES = 128 * 64 * 2;     // 16 KB
static constexpr uint32_t STAGE_BYTES = 2 * A_BYTES;  // 32 KB
static constexpr uint32_t BAR_OFF = 3 * STAGE_BYTES;  // 96 KB
static constexpr uint32_t SMEM_BYTES = BAR_OFF + 64;  // + barrier block

#define FULL_BAR(sb, s) ((sb) + BAR_OFF + (uint32_t)(s) * 16)
#define FREE_BAR(sb, s) ((sb) + BAR_OFF + (uint32_t)(s) * 16 + 8)

__device__ __forceinline__ void issue_stage(
    const __half* __restrict__ gA, const __half* __restrict__ gB,
    uint32_t sb, int kc, int s, int m0, int n0, int tid)
{
    const uint32_t stage = sb + (uint32_t)s * STAGE_BYTES;
    const int k0 = kc * 64;
#pragma unroll
    for (int i = 0; i < 8; ++i) {                      // A: 1024 16B chunks
        int id = tid + i * 128;
        int r = id >> 3, c = id & 7;
        const __half* src = gA + (size_t)(m0 + r) * IN_F + k0 + c * 8;
        uint32_t dst = stage + r * 128 + ((c ^ (r & 7)) * 16);
        cp_async16(dst, src);
    }
#pragma unroll
    for (int i = 0; i < 8; ++i) {                      // B: 1024 16B chunks
        int id = tid + i * 128;
        int r = id >> 3, c = id & 7;
        const __half* src = gB + (size_t)(n0 + r) * IN_F + k0 + c * 8;
        uint32_t dst = stage + A_BYTES + r * 128 + ((c ^ (r & 7)) * 16);
        cp_async16(dst, src);
    }
}

__global__ void __launch_bounds__(128, 2)
gemm_kernel(const float* __restrict__ bias, float* __restrict__ out)
{
    extern __shared__ char smem[];
    const uint32_t sb = smem_u32(smem);
    const int tid = threadIdx.x;
    const int lane = tid & 31;
    const int warp = tid >> 5;                // 0..3
    const int wm = warp >> 1;                 // 0..1 -> 64-row M slab
    const int wn = warp & 1;                  // 0..1 -> 64-col N slab
    const int n0 = blockIdx.x * 128;
    const int m0 = blockIdx.y * 128;
    const __half* gA = g_xh;
    const __half* gB = g_wh;

    // barriers
    if (tid == 0) {
#pragma unroll
        for (int s = 0; s < 3; ++s) {
            mbar_init(FULL_BAR(sb, s), 128);
            mbar_init(FREE_BAR(sb, s), 4);
        }
    }
    __syncthreads();

    // A ldmatrix: rows wm*64 + mt*16 + (lane&15); k sub-chunk = lane>>4
    const int rowA = wm * 64 + (lane & 15);
    const uint32_t aOff = (uint32_t)rowA * 128
                        + ((((lane >> 4) ^ (rowA & 7)) & 7) * 16);
    // B ldmatrix (paired x4 = two 8-wide n-tiles per load, 4 loads = 64 cols)
    const int rowB = wn * 64 + ((lane >> 4) << 3) + (lane & 7);
    const uint32_t cB = (uint32_t)((lane >> 3) & 1);
    const uint32_t bOff = (uint32_t)rowB * 128
                        + (((cB ^ (rowB & 7)) & 7) * 16);

    float acc[32][4];                          // [mt*8+nt][4]
#pragma unroll
    for (int i = 0; i < 32; ++i)
#pragma unroll
        for (int j = 0; j < 4; ++j) acc[i][j] = 0.0f;

    // prologue: fill stages 0,1 (first lap — no free-wait needed)
    issue_stage(gA, gB, sb, 0, 0, m0, n0, tid);
    cp_async_arrive_noinc(FULL_BAR(sb, 0));
    issue_stage(gA, gB, sb, 1, 1, m0, n0, tid);
    cp_async_arrive_noinc(FULL_BAR(sb, 1));

    int ps = 2, pp = 1;   // producer cursor; phase 1 -> first-lap waits pass
    int cs = 0, cph = 0;  // consumer cursor

#pragma unroll 1
    for (int c = 0; c < NCHUNK; ++c) {
        // ---- consumer: wait chunk c ready, preload ks=0 fragments ----
        mbar_wait(FULL_BAR(sb, cs), (uint32_t)cph);
        const uint32_t stage = sb + (uint32_t)cs * STAGE_BYTES;
        const uint32_t aBase = stage + aOff;
        const uint32_t bBase = stage + A_BYTES + bOff;

        uint32_t a[4][4], b[8][2];
#pragma unroll
        for (int mt = 0; mt < 4; ++mt)
            ldsm_x4(a[mt][0], a[mt][1], a[mt][2], a[mt][3], aBase + mt * 2048);
#pragma unroll
        for (int p = 0; p < 4; ++p)
            ldsm_x4(b[2 * p][0], b[2 * p][1], b[2 * p + 1][0], b[2 * p + 1][1],
                    bBase + p * 2048);

        // ---- producer stint: covered by the ks0 fragments already in regs ----
        if (c + 2 < NCHUNK) {
            mbar_wait(FREE_BAR(sb, ps), (uint32_t)pp);
            issue_stage(gA, gB, sb, c + 2, ps, m0, n0, tid);
            cp_async_arrive_noinc(FULL_BAR(sb, ps));
            if (++ps == 3) { ps = 0; pp ^= 1; }
        }

        // ---- ks=0 mma block ----
#pragma unroll
        for (int mt = 0; mt < 4; ++mt)
#pragma unroll
            for (int nt = 0; nt < 8; ++nt)
                mma16816(acc[mt * 8 + nt], a[mt], b[nt]);

        // ---- ks=1..3 ----
#pragma unroll
        for (int ks = 1; ks < 4; ++ks) {
            const uint32_t kx = (uint32_t)ks << 5;
#pragma unroll
            for (int mt = 0; mt < 4; ++mt)
                ldsm_x4(a[mt][0], a[mt][1], a[mt][2], a[mt][3],
                        (aBase + mt * 2048) ^ kx);
#pragma unroll
            for (int p = 0; p < 4; ++p)
                ldsm_x4(b[2 * p][0], b[2 * p][1], b[2 * p + 1][0], b[2 * p + 1][1],
                        (bBase + p * 2048) ^ kx);
            if (ks == 3 && lane == 0)          // last smem read done -> free stage
                mbar_arrive(FREE_BAR(sb, cs));
#pragma unroll
            for (int mt = 0; mt < 4; ++mt)
#pragma unroll
                for (int nt = 0; nt < 8; ++nt)
                    mma16816(acc[mt * 8 + nt], a[mt], b[nt]);
        }
        if (++cs == 3) { cs = 0; cph ^= 1; }
    }

    // epilogue: add bias, store fp32
    const int r0 = m0 + wm * 64 + (lane >> 2);
    const int c0base = n0 + wn * 64 + 2 * (lane & 3);
#pragma unroll
    for (int nt = 0; nt < 8; ++nt) {
        const int col = c0base + nt * 8;
        const float b0 = __ldg(bias + col);
        const float b1 = __ldg(bias + col + 1);
#pragma unroll
        for (int mt = 0; mt < 4; ++mt) {
            const float* cc = acc[mt * 8 + nt];
            const int row = r0 + mt * 16;
            float2 v0 = { cc[0] + b0, cc[1] + b1 };
            float2 v1 = { cc[2] + b0, cc[3] + b1 };
            *reinterpret_cast<float2*>(out + (size_t)row * OUT_F + col) = v0;
            *reinterpret_cast<float2*>(out + (size_t)(row + 8) * OUT_F + col) = v1;
        }
    }
}

// ============================ host launcher ================================
extern "C" void kernel_launch(void* const* d_in, const int* in_sizes, int n_in,
                              void* d_out, int out_size) {
    (void)in_sizes; (void)n_in; (void)out_size;
    const float* x      = (const float*)d_in[0];
    const int*   packed = (const int*)  d_in[1];
    const float* alpha  = (const float*)d_in[2];
    const float* mu     = (const float*)d_in[3];
    const float* bias   = (const float*)d_in[4];
    const float* loraA  = (const float*)d_in[5];
    const float* loraB  = (const float*)d_in[6];
    float* out = (float*)d_out;

    cudaFuncSetAttribute(gemm_kernel, cudaFuncAttributeMaxDynamicSharedMemorySize,
                         SMEM_BYTES);

    prep_fused_kernel<<<PREP_BLOCKS + W_BLOCKS, 256>>>(x, packed, alpha, mu,
                                                       loraA, loraB);
    dim3 grid(OUT_F / 128, TOKENS / 128);    // (32, 64)
    gemm_kernel<<<grid, 128, SMEM_BYTES>>>(bias, out);
}